// round 15
// baseline (speedup 1.0000x reference)
#include <cuda_runtime.h>
#include <math.h>
#include <stdint.h>

#define BB 64
#define SS 100
#define EE 512
#define HH 1024
#define VT 32000
#define GRID 256
#define NSA 16      // h0 GEMM splits (K=1024, 64 each)
#define NSB 20      // decoder splits: 12 x-slices(128) + 8 h0-slices(128)

// ---------------- scratch ----------------
__device__ float g_mean[BB * HH];
__device__ float g_h0[BB * HH];
__device__ float g_x[BB * (EE + HH)];
__device__ float4 g_partA[BB * (HH / 4) * NSA];   // [(o)*16 + p]
__device__ float4 g_partB[BB * (HH / 4) * NSB];   // [(o)*20 + p]
__device__ unsigned g_bar_cnt;

// ---------------- helpers ----------------
__device__ __forceinline__ uint32_t smem_u32(const void* p) {
    uint32_t a;
    asm("{ .reg .u64 t; cvta.to.shared.u64 t, %1; cvt.u32.u64 %0, t; }" : "=r"(a) : "l"(p));
    return a;
}
__device__ __forceinline__ uint32_t f2tf32(float x) {
    uint32_t u;
    asm("cvt.rna.tf32.f32 %0, %1;" : "=r"(u) : "f"(x));
    return u;
}
__device__ __forceinline__ void cp_async16(uint32_t saddr, const void* g) {
    asm volatile("cp.async.ca.shared.global [%0], [%1], 16;" :: "r"(saddr), "l"(g) : "memory");
}
__device__ __forceinline__ void cp_commit() {
    asm volatile("cp.async.commit_group;" ::: "memory");
}
__device__ __forceinline__ void cp_wait1() {
    asm volatile("cp.async.wait_group 1;" ::: "memory");
}
__device__ __forceinline__ void mma_tf32(float d[4], const uint32_t a[4], const uint32_t b[2]) {
    asm volatile(
        "mma.sync.aligned.m16n8k8.row.col.f32.tf32.tf32.f32 "
        "{%0,%1,%2,%3}, {%4,%5,%6,%7}, {%8,%9}, {%0,%1,%2,%3};"
        : "+f"(d[0]), "+f"(d[1]), "+f"(d[2]), "+f"(d[3])
        : "r"(a[0]), "r"(a[1]), "r"(a[2]), "r"(a[3]), "r"(b[0]), "r"(b[1]));
}
__device__ __forceinline__ float4 f4add(float4 a, float4 b) {
    return make_float4(a.x + b.x, a.y + b.y, a.z + b.z, a.w + b.w);
}

// grid barrier: all GRID CTAs co-resident (launch_bounds(256,2), 55KB smem)
__device__ __forceinline__ void gbar(unsigned target) {
    __syncthreads();
    __threadfence();
    if (threadIdx.x == 0) {
        atomicAdd(&g_bar_cnt, 1u);
        while (*(volatile unsigned*)&g_bar_cnt < target) __nanosleep(64);
    }
    __syncthreads();
}

__global__ void init_bar() { g_bar_cnt = 0; }

// ---------------- tf32 GEMM tile bodies ----------------
#define PLDA 36
#define PBUF (64 * PLDA + 128 * PLDA)
#define GTC_SMEM (2 * PBUF * 4)

// split-K tile -> transposed partials (p = slice index, pstride = NSA/NSB)
__device__ void gemm_sk_tile(float* sm, int tid, int n0, int kbase, int kslice,
    const float* __restrict__ A0, const float* __restrict__ B0, int K0,
    float4* __restrict__ partbase, int pstride, int p)
{
    const int wid  = tid >> 5;
    const int lane = tid & 31;
    const int wm   = wid & 1;
    const int wn   = wid >> 1;
    const int lrow = tid >> 3;
    const int lf4  = tid & 7;

    float d[2][4][4];
    #pragma unroll
    for (int i = 0; i < 2; i++)
        #pragma unroll
        for (int j = 0; j < 4; j++)
            #pragma unroll
            for (int k = 0; k < 4; k++) d[i][j][k] = 0.f;

    auto load_tile = [&](int buf, int gk) {
        float* as = sm + buf * PBUF;
        float* bs = as + 64 * PLDA;
        #pragma unroll
        for (int i = 0; i < 2; i++) {
            int row = lrow + i * 32;
            cp_async16(smem_u32(&as[row * PLDA + lf4 * 4]),
                       &A0[(size_t)row * K0 + gk + lf4 * 4]);
        }
        #pragma unroll
        for (int i = 0; i < 4; i++) {
            int row = lrow + i * 32;
            cp_async16(smem_u32(&bs[row * PLDA + lf4 * 4]),
                       &B0[(size_t)(n0 + row) * K0 + gk + lf4 * 4]);
        }
        cp_commit();
    };

    const int NT = kslice / 32;
    load_tile(0, kbase);
    for (int t = 0; t < NT; t++) {
        if (t + 1 < NT) load_tile((t + 1) & 1, kbase + (t + 1) * 32);
        else cp_commit();
        cp_wait1();
        __syncthreads();
        const float* as = sm + (t & 1) * PBUF;
        const float* bs = as + 64 * PLDA;
        const int r = lane >> 2, c = lane & 3;
        #pragma unroll
        for (int k8 = 0; k8 < 4; k8++) {
            int kc = k8 * 8;
            uint32_t af[2][4], bf[4][2];
            #pragma unroll
            for (int mm = 0; mm < 2; mm++) {
                int mb = wm * 32 + mm * 16;
                af[mm][0] = f2tf32(as[(mb + r)     * PLDA + kc + c]);
                af[mm][1] = f2tf32(as[(mb + r + 8) * PLDA + kc + c]);
                af[mm][2] = f2tf32(as[(mb + r)     * PLDA + kc + c + 4]);
                af[mm][3] = f2tf32(as[(mb + r + 8) * PLDA + kc + c + 4]);
            }
            #pragma unroll
            for (int nn = 0; nn < 4; nn++) {
                int nb = wn * 32 + nn * 8;
                bf[nn][0] = f2tf32(bs[(nb + r) * PLDA + kc + c]);
                bf[nn][1] = f2tf32(bs[(nb + r) * PLDA + kc + c + 4]);
            }
            #pragma unroll
            for (int mm = 0; mm < 2; mm++)
                #pragma unroll
                for (int nn = 0; nn < 4; nn++)
                    mma_tf32(d[mm][nn], af[mm], bf[nn]);
        }
        __syncthreads();
    }

    const int nq = HH >> 2;
    #pragma unroll
    for (int mm = 0; mm < 2; mm++) {
        int m = wm * 32 + mm * 16 + (lane >> 2);
        #pragma unroll
        for (int nn = 0; nn < 4; nn++) {
            int n = n0 + wn * 32 + nn * 8 + (lane & 3) * 2;
            int w = n & 3;
            float* f0 = (float*)&partbase[((size_t)m * nq + (n >> 2)) * pstride + p];
            float* f1 = (float*)&partbase[((size_t)(m + 8) * nq + (n >> 2)) * pstride + p];
            *(float2*)(f0 + w) = make_float2(d[mm][nn][0], d[mm][nn][1]);
            *(float2*)(f1 + w) = make_float2(d[mm][nn][2], d[mm][nn][3]);
        }
    }
}

// projection tile -> C (+bias)
__device__ void gemm_proj_tile(float* sm, int tid, int n0,
    const float* __restrict__ A, const float* __restrict__ Bm,
    const float* __restrict__ bias, float* __restrict__ C)
{
    const int wid  = tid >> 5;
    const int lane = tid & 31;
    const int wm   = wid & 1;
    const int wn   = wid >> 1;
    const int lrow = tid >> 3;
    const int lf4  = tid & 7;

    float d[2][4][4];
    #pragma unroll
    for (int i = 0; i < 2; i++)
        #pragma unroll
        for (int j = 0; j < 4; j++)
            #pragma unroll
            for (int k = 0; k < 4; k++) d[i][j][k] = 0.f;

    auto load_tile = [&](int buf, int kb) {
        float* as = sm + buf * PBUF;
        float* bs = as + 64 * PLDA;
        #pragma unroll
        for (int i = 0; i < 2; i++) {
            int row = lrow + i * 32;
            cp_async16(smem_u32(&as[row * PLDA + lf4 * 4]),
                       &A[(size_t)row * HH + kb + lf4 * 4]);
        }
        #pragma unroll
        for (int i = 0; i < 4; i++) {
            int row = lrow + i * 32;
            cp_async16(smem_u32(&bs[row * PLDA + lf4 * 4]),
                       &Bm[(size_t)(n0 + row) * HH + kb + lf4 * 4]);
        }
        cp_commit();
    };

    const int NT = HH / 32;
    load_tile(0, 0);
    for (int t = 0; t < NT; t++) {
        if (t + 1 < NT) load_tile((t + 1) & 1, (t + 1) * 32);
        else cp_commit();
        cp_wait1();
        __syncthreads();
        const float* as = sm + (t & 1) * PBUF;
        const float* bs = as + 64 * PLDA;
        const int r = lane >> 2, c = lane & 3;
        #pragma unroll
        for (int k8 = 0; k8 < 4; k8++) {
            int kc = k8 * 8;
            uint32_t af[2][4], bf[4][2];
            #pragma unroll
            for (int mm = 0; mm < 2; mm++) {
                int mb = wm * 32 + mm * 16;
                af[mm][0] = f2tf32(as[(mb + r)     * PLDA + kc + c]);
                af[mm][1] = f2tf32(as[(mb + r + 8) * PLDA + kc + c]);
                af[mm][2] = f2tf32(as[(mb + r)     * PLDA + kc + c + 4]);
                af[mm][3] = f2tf32(as[(mb + r + 8) * PLDA + kc + c + 4]);
            }
            #pragma unroll
            for (int nn = 0; nn < 4; nn++) {
                int nb = wn * 32 + nn * 8;
                bf[nn][0] = f2tf32(bs[(nb + r) * PLDA + kc + c]);
                bf[nn][1] = f2tf32(bs[(nb + r) * PLDA + kc + c + 4]);
            }
            #pragma unroll
            for (int mm = 0; mm < 2; mm++)
                #pragma unroll
                for (int nn = 0; nn < 4; nn++)
                    mma_tf32(d[mm][nn], af[mm], bf[nn]);
        }
        __syncthreads();
    }

    #pragma unroll
    for (int mm = 0; mm < 2; mm++) {
        int m = wm * 32 + mm * 16 + (lane >> 2);
        #pragma unroll
        for (int nn = 0; nn < 4; nn++) {
            int n = n0 + wn * 32 + nn * 8 + (lane & 3) * 2;
            float2 bv = *(const float2*)&bias[n];
            *(float2*)&C[(size_t)m * VT + n] =
                make_float2(d[mm][nn][0] + bv.x, d[mm][nn][1] + bv.y);
            *(float2*)&C[(size_t)(m + 8) * VT + n] =
                make_float2(d[mm][nn][2] + bv.x, d[mm][nn][3] + bv.y);
        }
    }
}

// ---------------- the mega kernel ----------------
__global__ __launch_bounds__(256, 2) void mega_kernel(
    const int* __restrict__ src, const int* __restrict__ pos, const int* __restrict__ tgt,
    const float* __restrict__ emb_in, const float* __restrict__ emb_out,
    const float* __restrict__ emb_pos,
    const float* __restrict__ W_scale, const float* __restrict__ b_scale,
    const float* __restrict__ W_ih, const float* __restrict__ b_ih,
    const float* __restrict__ W_hh, const float* __restrict__ b_hh,
    const float* __restrict__ W_proj, const float* __restrict__ b_proj,
    float* __restrict__ out, float* __restrict__ h)
{
    extern __shared__ float sm[];
    __shared__ float s_h0[HH];
    __shared__ float s_en[112];
    __shared__ float s_w[112];
    __shared__ int s_sidx[112], s_pidx[112];

    const int cta = blockIdx.x;
    const int tid = threadIdx.x;
    const int lane = tid & 31;
    const int warp = tid >> 5;
    unsigned gen = 0;

    // ---- P0: mean per b (ctas 0..63); x_emb copy (ctas 64..127) ----
    if (cta < BB) {
        int b = cta;
        if (tid < SS) s_sidx[tid] = src[b * SS + tid];
        if (tid >= 128 && tid < 128 + SS) s_pidx[tid - 128] = pos[b * SS + tid - 128];
        __syncthreads();
        const int half = tid >= 128;
        const int cc = half ? tid * 4 - EE : tid * 4;
        const float* base = half ? emb_pos : emb_in;
        const int* idx = half ? s_pidx : s_sidx;
        float4 acc = make_float4(0.f, 0.f, 0.f, 0.f);
        #pragma unroll 4
        for (int i = 0; i < SS; i++)
            acc = f4add(acc, *(const float4*)(base + (size_t)idx[i] * EE + cc));
        const float inv = 1.0f / SS;
        acc.x *= inv; acc.y *= inv; acc.z *= inv; acc.w *= inv;
        *(float4*)(g_mean + b * HH + tid * 4) = acc;
    } else if (cta < 2 * BB) {
        int b = cta - BB;
        if (tid < 128) {
            const float4* w = (const float4*)(emb_out + (size_t)tgt[b] * EE);
            ((float4*)(g_x + b * (EE + HH)))[tid] = w[tid];
        }
    }
    gbar(++gen * GRID);

    // ---- P1: h0 GEMM (ctas 0..127): 16 splits x 8 n-tiles ----
    if (cta < 8 * NSA) {
        int bx = cta & 7, p = cta >> 3;
        gemm_sk_tile(sm, tid, bx * 128, p * (HH / NSA), HH / NSA,
                     g_mean, W_scale, HH, g_partA, NSA, p);
    }
    gbar(++gen * GRID);

    // ---- P2: h0 reduce (all 256): 4 lanes/output, 4 partials each ----
    {
        const int gw = cta * 8 + warp;
        const int o  = gw * 8 + (lane >> 2);
        const int q  = lane & 3;
        const int nq = HH >> 2;
        const int m  = o / nq;
        const int n4 = o - m * nq;
        const float4* sp = &g_partA[(size_t)o * NSA + q * 4];
        float4 s = __ldcg(sp);
        s = f4add(s, __ldcg(sp + 1));
        s = f4add(s, __ldcg(sp + 2));
        s = f4add(s, __ldcg(sp + 3));
        #pragma unroll
        for (int off = 2; off >= 1; off >>= 1) {
            s.x += __shfl_down_sync(0xffffffffu, s.x, off, 4);
            s.y += __shfl_down_sync(0xffffffffu, s.y, off, 4);
            s.z += __shfl_down_sync(0xffffffffu, s.z, off, 4);
            s.w += __shfl_down_sync(0xffffffffu, s.w, off, 4);
        }
        if (q == 0) {
            s = f4add(s, *(const float4*)&b_scale[n4 * 4]);
            *(float4*)&g_h0[(size_t)m * HH + n4 * 4] = s;
        }
    }
    gbar(++gen * GRID);

    // ---- P3: fused attention (ctas 0..63) || h0@W_hh GEMM (ctas 64..127) ----
    if (cta < BB) {
        int b = cta;
        for (int c = tid; c < HH; c += 256) s_h0[c] = g_h0[b * HH + c];
        if (tid < SS) s_sidx[tid] = src[b * SS + tid];
        if (tid >= 128 && tid < 128 + SS) s_pidx[tid - 128] = pos[b * SS + tid - 128];
        __syncthreads();
        // energies: warp w -> s = w, w+8, ...
        for (int s = warp; s < SS; s += 8) {
            const float4* rw = (const float4*)(emb_in  + (size_t)s_sidx[s] * EE);
            const float4* rp = (const float4*)(emb_pos + (size_t)s_pidx[s] * EE);
            float sum = 0.f;
            #pragma unroll
            for (int e = 0; e < 8; e++) {
                int f4 = lane + e * 32;
                float4 v = (f4 < 128) ? rw[f4] : rp[f4 - 128];
                int c = f4 * 4;
                sum = fmaf(s_h0[c],   v.x, sum);
                sum = fmaf(s_h0[c+1], v.y, sum);
                sum = fmaf(s_h0[c+2], v.z, sum);
                sum = fmaf(s_h0[c+3], v.w, sum);
            }
            #pragma unroll
            for (int o = 16; o; o >>= 1) sum += __shfl_xor_sync(0xffffffffu, sum, o);
            if (lane == 0) s_en[s] = sum;
        }
        __syncthreads();
        // softmax (warp 0), weights include 1/S
        if (tid < 32) {
            float e[4];
            float m = -1e30f;
            #pragma unroll
            for (int i = 0; i < 4; i++) {
                int s = lane + i * 32;
                e[i] = (s < SS) ? s_en[s] : -1e30f;
                m = fmaxf(m, e[i]);
            }
            #pragma unroll
            for (int o = 16; o; o >>= 1) m = fmaxf(m, __shfl_xor_sync(0xffffffffu, m, o));
            float sum = 0.f;
            #pragma unroll
            for (int i = 0; i < 4; i++) { e[i] = __expf(e[i] - m); sum += e[i]; }
            #pragma unroll
            for (int o = 16; o; o >>= 1) sum += __shfl_xor_sync(0xffffffffu, sum, o);
            float inv = 1.0f / (sum * (float)SS);
            #pragma unroll
            for (int i = 0; i < 4; i++) {
                int s = lane + i * 32;
                if (s < SS) s_w[s] = e[i] * inv;
            }
        }
        __syncthreads();
        // context -> g_x[b][EE + c]
        const int half = tid >= 128;
        const int cc = half ? tid * 4 - EE : tid * 4;
        const float* base = half ? emb_pos : emb_in;
        const int* idx = half ? s_pidx : s_sidx;
        float4 acc = make_float4(0.f, 0.f, 0.f, 0.f);
        #pragma unroll 4
        for (int i = 0; i < SS; i++) {
            float ws = s_w[i];
            float4 v = *(const float4*)(base + (size_t)idx[i] * EE + cc);
            acc.x = fmaf(ws, v.x, acc.x); acc.y = fmaf(ws, v.y, acc.y);
            acc.z = fmaf(ws, v.z, acc.z); acc.w = fmaf(ws, v.w, acc.w);
        }
        *(float4*)(g_x + (size_t)b * (EE + HH) + EE + tid * 4) = acc;
    } else if (cta < 2 * BB) {
        int idx = cta - BB;
        int bx = idx & 7, sl = idx >> 3;            // sl 0..7
        gemm_sk_tile(sm, tid, bx * 128, sl * 128, 128,
                     g_h0, W_hh, HH, g_partB, NSB, 12 + sl);
    }
    gbar(++gen * GRID);

    // ---- P4: decoder x-part GEMM (ctas 0..95): 12 slices x 8 n-tiles ----
    if (cta < 96) {
        int bx = cta & 7, sl = cta >> 3;            // sl 0..11
        gemm_sk_tile(sm, tid, bx * 128, sl * 128, 128,
                     g_x, W_ih, EE + HH, g_partB, NSB, sl);
    }
    gbar(++gen * GRID);

    // ---- P5: decoder reduce (all 256): 4 lanes/output, 5 partials each, tanh ----
    {
        const int gw = cta * 8 + warp;
        const int o  = gw * 8 + (lane >> 2);
        const int q  = lane & 3;
        const int nq = HH >> 2;
        const int m  = o / nq;
        const int n4 = o - m * nq;
        const float4* sp = &g_partB[(size_t)o * NSB + q * 5];
        float4 s = __ldcg(sp);
        s = f4add(s, __ldcg(sp + 1));
        s = f4add(s, __ldcg(sp + 2));
        s = f4add(s, __ldcg(sp + 3));
        s = f4add(s, __ldcg(sp + 4));
        #pragma unroll
        for (int off = 2; off >= 1; off >>= 1) {
            s.x += __shfl_down_sync(0xffffffffu, s.x, off, 4);
            s.y += __shfl_down_sync(0xffffffffu, s.y, off, 4);
            s.z += __shfl_down_sync(0xffffffffu, s.z, off, 4);
            s.w += __shfl_down_sync(0xffffffffu, s.w, off, 4);
        }
        if (q == 0) {
            s = f4add(s, *(const float4*)&b_ih[n4 * 4]);
            s = f4add(s, *(const float4*)&b_hh[n4 * 4]);
            s.x = tanhf(s.x); s.y = tanhf(s.y); s.z = tanhf(s.z); s.w = tanhf(s.w);
            *(float4*)&h[(size_t)m * HH + n4 * 4] = s;
        }
    }
    gbar(++gen * GRID);

    // ---- P6: projection (ctas 0..249) ----
    if (cta < VT / 128) {
        gemm_proj_tile(sm, tid, cta * 128, h, W_proj, b_proj, out);
    }
}

// ---------------- launch ----------------
extern "C" void kernel_launch(void* const* d_in, const int* in_sizes, int n_in,
                              void* d_out, int out_size)
{
    const int* src = (const int*)d_in[0];
    const int* pos = (const int*)d_in[1];
    const int* tgt = (const int*)d_in[2];

    int iE = -1;
    for (int i = 3; i < n_in; i++) {
        if (in_sizes[i] == 32000 * 512) { iE = i; break; }
    }
    const float* emb_in  = (const float*)d_in[iE + 0];
    const float* emb_out = (const float*)d_in[iE + 1];
    const float* emb_pos = (const float*)d_in[iE + 2];
    const float* W_scale = (const float*)d_in[iE + 3];
    const float* b_scale = (const float*)d_in[iE + 4];
    const float* W_ih    = (const float*)d_in[iE + 5];
    const float* b_ih    = (const float*)d_in[iE + 6];
    const float* W_hh    = (const float*)d_in[iE + 7];
    const float* b_hh    = (const float*)d_in[iE + 8];
    const float* W_proj  = (const float*)d_in[iE + 9];
    const float* b_proj  = (const float*)d_in[iE + 10];

    float* out = (float*)d_out;            // [B,VT]
    float* h   = out + (size_t)BB * VT;    // [B,H]

    cudaFuncSetAttribute(mega_kernel,
                         cudaFuncAttributeMaxDynamicSharedMemorySize, GTC_SMEM);

    init_bar<<<1, 1>>>();
    mega_kernel<<<GRID, 256, GTC_SMEM>>>(
        src, pos, tgt, emb_in, emb_out, emb_pos,
        W_scale, b_scale, W_ih, b_ih, W_hh, b_hh, W_proj, b_proj,
        out, h);

    (void)out_size;
}

// round 16
// speedup vs baseline: 1.1441x; 1.1441x over previous
#include <cuda_runtime.h>
#include <math.h>
#include <stdint.h>

#define BB 64
#define SS 100
#define EE 512
#define HH 1024
#define VT 32000
#define NSPLIT 16
#define SCH 4            // s-chunks for mean/context partials

// ---------------- scratch ----------------
__device__ float g_mpart[SCH * BB * HH];        // mean partials (unscaled sums)
__device__ float g_mean[BB * HH];
__device__ float g_h0[BB * HH];
__device__ float g_en[BB * SS];                 // energies
__device__ float g_cpart[SCH * BB * HH];        // context partials
__device__ float g_x[BB * (EE + HH)];           // decoder input concat
__device__ float g_part[NSPLIT * BB * HH];      // split-K partials

// ---------------- helpers ----------------
__device__ __forceinline__ uint32_t smem_u32(const void* p) {
    uint32_t a;
    asm("{ .reg .u64 t; cvta.to.shared.u64 t, %1; cvt.u32.u64 %0, t; }" : "=r"(a) : "l"(p));
    return a;
}
__device__ __forceinline__ uint32_t f2tf32(float x) {
    uint32_t u;
    asm("cvt.rna.tf32.f32 %0, %1;" : "=r"(u) : "f"(x));
    return u;
}
__device__ __forceinline__ void cp_async16(uint32_t saddr, const void* g) {
    asm volatile("cp.async.ca.shared.global [%0], [%1], 16;" :: "r"(saddr), "l"(g) : "memory");
}
__device__ __forceinline__ void cp_commit() {
    asm volatile("cp.async.commit_group;" ::: "memory");
}
__device__ __forceinline__ void cp_wait1() {
    asm volatile("cp.async.wait_group 1;" ::: "memory");
}
__device__ __forceinline__ void cp_wait2() {
    asm volatile("cp.async.wait_group 2;" ::: "memory");
}
__device__ __forceinline__ void mma_tf32(float d[4], const uint32_t a[4], const uint32_t b[2]) {
    asm volatile(
        "mma.sync.aligned.m16n8k8.row.col.f32.tf32.tf32.f32 "
        "{%0,%1,%2,%3}, {%4,%5,%6,%7}, {%8,%9}, {%0,%1,%2,%3};"
        : "+f"(d[0]), "+f"(d[1]), "+f"(d[2]), "+f"(d[3])
        : "r"(a[0]), "r"(a[1]), "r"(a[2]), "r"(a[3]), "r"(b[0]), "r"(b[1]));
}
__device__ __forceinline__ float4 f4add(float4 a, float4 b) {
    return make_float4(a.x + b.x, a.y + b.y, a.z + b.z, a.w + b.w);
}

// ---------------- 2a. mean partials (gather directly from embeddings) ----------------
__global__ __launch_bounds__(256) void mean_part_kernel(
    const int* __restrict__ src, const int* __restrict__ pos,
    const float* __restrict__ emb_in, const float* __restrict__ emb_pos)
{
    __shared__ int sidx[32], pidx[32];
    int b   = blockIdx.x;
    int y   = blockIdx.y;
    int tid = threadIdx.x;
    int s0  = y * (SS / SCH);
    if (tid >= 32 && tid < 32 + SS / SCH) sidx[tid - 32] = src[b * SS + s0 + tid - 32];
    if (tid >= 64 && tid < 64 + SS / SCH) pidx[tid - 64] = pos[b * SS + s0 + tid - 64];
    __syncthreads();

    const int half = tid >= 128;
    const int cc = half ? tid * 4 - EE : tid * 4;
    const float* base = half ? emb_pos : emb_in;
    const int* idx = half ? pidx : sidx;
    float4 acc = make_float4(0.f, 0.f, 0.f, 0.f);
    #pragma unroll 5
    for (int i = 0; i < SS / SCH; i++) {
        float4 v = *(const float4*)(base + (size_t)idx[i] * EE + cc);
        acc = f4add(acc, v);
    }
    *(float4*)(g_mpart + ((size_t)y * BB + b) * HH + tid * 4) = acc;
}

// ---------------- 2b. mean reduce ----------------
__global__ __launch_bounds__(256) void mean_red_kernel()
{
    int b  = blockIdx.x;
    int c4 = threadIdx.x * 4;
    float4 s = make_float4(0.f, 0.f, 0.f, 0.f);
    #pragma unroll
    for (int y = 0; y < SCH; y++) {
        float4 v = *(const float4*)(g_mpart + ((size_t)y * BB + b) * HH + c4);
        s = f4add(s, v);
    }
    const float inv = 1.0f / SS;
    s.x *= inv; s.y *= inv; s.z *= inv; s.w *= inv;
    *(float4*)(g_mean + b * HH + c4) = s;
}

// ---------------- tf32 split-K GEMM: part[ksplit][64][N] = A@B^T slice ----------------
#define PLDA 36
#define PBUF (64 * PLDA + 128 * PLDA)
#define GTC_SMEM (2 * PBUF * 4)

__global__ __launch_bounds__(256, 2) void gemm64tc_kernel(
    const float* __restrict__ A0, const float* __restrict__ B0, int K0,
    const float* __restrict__ A1, const float* __restrict__ B1, int K1,
    float* __restrict__ part, int N, int kslice)
{
    extern __shared__ float sm[];
    const int tid  = threadIdx.x;
    const int wid  = tid >> 5;
    const int lane = tid & 31;
    const int n0   = blockIdx.x * 128;
    const int kbase = blockIdx.y * kslice;
    const int wm   = wid & 1;
    const int wn   = wid >> 1;
    const int lrow = tid >> 3;
    const int lf4  = tid & 7;

    float d[2][4][4];
    #pragma unroll
    for (int i = 0; i < 2; i++)
        #pragma unroll
        for (int j = 0; j < 4; j++)
            #pragma unroll
            for (int k = 0; k < 4; k++) d[i][j][k] = 0.f;

    auto load_tile = [&](int buf, int gk) {
        const float* A; const float* Bv; int K, kl;
        if (gk < K0) { A = A0; Bv = B0; K = K0; kl = gk; }
        else         { A = A1; Bv = B1; K = K1; kl = gk - K0; }
        float* as = sm + buf * PBUF;
        float* bs = as + 64 * PLDA;
        #pragma unroll
        for (int i = 0; i < 2; i++) {
            int row = lrow + i * 32;
            cp_async16(smem_u32(&as[row * PLDA + lf4 * 4]),
                       &A[(size_t)row * K + kl + lf4 * 4]);
        }
        #pragma unroll
        for (int i = 0; i < 4; i++) {
            int row = lrow + i * 32;
            cp_async16(smem_u32(&bs[row * PLDA + lf4 * 4]),
                       &Bv[(size_t)(n0 + row) * K + kl + lf4 * 4]);
        }
        cp_commit();
    };

    const int NT = kslice / 32;
    load_tile(0, kbase);
    for (int t = 0; t < NT; t++) {
        if (t + 1 < NT) load_tile((t + 1) & 1, kbase + (t + 1) * 32);
        else cp_commit();
        cp_wait1();
        __syncthreads();
        const float* as = sm + (t & 1) * PBUF;
        const float* bs = as + 64 * PLDA;
        const int r = lane >> 2, c = lane & 3;
        #pragma unroll
        for (int k8 = 0; k8 < 4; k8++) {
            int kc = k8 * 8;
            uint32_t af[2][4], bf[4][2];
            #pragma unroll
            for (int mm = 0; mm < 2; mm++) {
                int mb = wm * 32 + mm * 16;
                af[mm][0] = f2tf32(as[(mb + r)     * PLDA + kc + c]);
                af[mm][1] = f2tf32(as[(mb + r + 8) * PLDA + kc + c]);
                af[mm][2] = f2tf32(as[(mb + r)     * PLDA + kc + c + 4]);
                af[mm][3] = f2tf32(as[(mb + r + 8) * PLDA + kc + c + 4]);
            }
            #pragma unroll
            for (int nn = 0; nn < 4; nn++) {
                int nb = wn * 32 + nn * 8;
                bf[nn][0] = f2tf32(bs[(nb + r) * PLDA + kc + c]);
                bf[nn][1] = f2tf32(bs[(nb + r) * PLDA + kc + c + 4]);
            }
            #pragma unroll
            for (int mm = 0; mm < 2; mm++)
                #pragma unroll
                for (int nn = 0; nn < 4; nn++)
                    mma_tf32(d[mm][nn], af[mm], bf[nn]);
        }
        __syncthreads();
    }

    float* dst = part + (size_t)blockIdx.y * 64 * N;
    #pragma unroll
    for (int mm = 0; mm < 2; mm++) {
        int m = wm * 32 + mm * 16 + (lane >> 2);
        #pragma unroll
        for (int nn = 0; nn < 4; nn++) {
            int n = n0 + wn * 32 + nn * 8 + (lane & 3) * 2;
            *(float2*)&dst[(size_t)m * N + n]       = make_float2(d[mm][nn][0], d[mm][nn][1]);
            *(float2*)&dst[(size_t)(m + 8) * N + n] = make_float2(d[mm][nn][2], d[mm][nn][3]);
        }
    }
}

// ---------------- reduce partials + bias (+bias1) (+tanh) ----------------
// 4 lanes per float4 output: lane q sums partials 4q..4q+3, quad-shfl combine.
__global__ __launch_bounds__(256) void reduce_part_kernel(
    const float* __restrict__ bias0, const float* __restrict__ bias1,
    float* __restrict__ C, int N, int do_tanh)
{
    const int tid = threadIdx.x;
    const int q   = tid & 3;
    const int o   = blockIdx.x * 64 + (tid >> 2);
    const int nq  = N >> 2;
    const int m   = o / nq;
    const int n4  = o - m * nq;

    float4 s = make_float4(0.f, 0.f, 0.f, 0.f);
    #pragma unroll
    for (int i = 0; i < 4; i++) {
        int p = q * 4 + i;
        float4 v = *(const float4*)&g_part[((size_t)p * 64 + m) * N + n4 * 4];
        s = f4add(s, v);
    }
    #pragma unroll
    for (int off = 2; off >= 1; off >>= 1) {
        s.x += __shfl_down_sync(0xffffffffu, s.x, off, 4);
        s.y += __shfl_down_sync(0xffffffffu, s.y, off, 4);
        s.z += __shfl_down_sync(0xffffffffu, s.z, off, 4);
        s.w += __shfl_down_sync(0xffffffffu, s.w, off, 4);
    }
    if (q == 0) {
        float4 b0 = *(const float4*)&bias0[n4 * 4];
        s = f4add(s, b0);
        if (bias1) {
            float4 b1 = *(const float4*)&bias1[n4 * 4];
            s = f4add(s, b1);
        }
        if (do_tanh) {
            s.x = tanhf(s.x); s.y = tanhf(s.y); s.z = tanhf(s.z); s.w = tanhf(s.w);
        }
        *(float4*)&C[(size_t)m * N + n4 * 4] = s;
    }
}

// ---------------- 4a. energies (gather) ----------------
__global__ __launch_bounds__(256) void energy_kernel(
    const int* __restrict__ src, const int* __restrict__ pos,
    const float* __restrict__ emb_in, const float* __restrict__ emb_pos)
{
    __shared__ float h0s[HH];
    int b    = blockIdx.x;
    int tid  = threadIdx.x;
    int warp = tid >> 5;
    int lane = tid & 31;

    for (int c = tid; c < HH; c += 256) h0s[c] = g_h0[b * HH + c];
    __syncthreads();

    int s = blockIdx.y * 8 + warp;
    if (s < SS) {
        int si = __shfl_sync(0xffffffffu, lane == 0 ? src[b * SS + s] : 0, 0);
        int pi = __shfl_sync(0xffffffffu, lane == 0 ? pos[b * SS + s] : 0, 0);
        const float4* rw = (const float4*)(emb_in  + (size_t)si * EE);
        const float4* rp = (const float4*)(emb_pos + (size_t)pi * EE);
        float sum = 0.f;
        #pragma unroll
        for (int e = 0; e < 8; e++) {
            int f4 = lane + e * 32;
            float4 v = (f4 < 128) ? rw[f4] : rp[f4 - 128];
            int c = f4 * 4;
            sum = fmaf(h0s[c],   v.x, sum);
            sum = fmaf(h0s[c+1], v.y, sum);
            sum = fmaf(h0s[c+2], v.z, sum);
            sum = fmaf(h0s[c+3], v.w, sum);
        }
        #pragma unroll
        for (int o = 16; o; o >>= 1) sum += __shfl_xor_sync(0xffffffffu, sum, o);
        if (lane == 0) g_en[b * SS + s] = sum;
    }
}

// ---------------- 4b. context partials (softmax in-block, gather) ----------------
__global__ __launch_bounds__(256) void ctx_part_kernel(
    const int* __restrict__ src, const int* __restrict__ pos,
    const float* __restrict__ emb_in, const float* __restrict__ emb_pos)
{
    __shared__ float w[128];
    __shared__ int sidx[32], pidx[32];
    int b    = blockIdx.x;
    int y    = blockIdx.y;
    int tid  = threadIdx.x;
    int lane = tid & 31;
    int s0   = y * (SS / SCH);

    if (tid < 32) {
        float e[4];
        float m = -1e30f;
        #pragma unroll
        for (int i = 0; i < 4; i++) {
            int s = lane + i * 32;
            e[i] = (s < SS) ? g_en[b * SS + s] : -1e30f;
            m = fmaxf(m, e[i]);
        }
        #pragma unroll
        for (int o = 16; o; o >>= 1) m = fmaxf(m, __shfl_xor_sync(0xffffffffu, m, o));
        float sum = 0.f;
        #pragma unroll
        for (int i = 0; i < 4; i++) { e[i] = __expf(e[i] - m); sum += e[i]; }
        #pragma unroll
        for (int o = 16; o; o >>= 1) sum += __shfl_xor_sync(0xffffffffu, sum, o);
        float inv = 1.0f / (sum * (float)SS);
        #pragma unroll
        for (int i = 0; i < 4; i++) {
            int s = lane + i * 32;
            if (s < 128) w[s] = e[i] * inv;
        }
    }
    if (tid >= 32 && tid < 32 + SS / SCH) sidx[tid - 32] = src[b * SS + s0 + tid - 32];
    if (tid >= 64 && tid < 64 + SS / SCH) pidx[tid - 64] = pos[b * SS + s0 + tid - 64];
    __syncthreads();

    const int half = tid >= 128;
    const int cc = half ? tid * 4 - EE : tid * 4;
    const float* base = half ? emb_pos : emb_in;
    const int* idx = half ? pidx : sidx;
    float4 acc = make_float4(0.f, 0.f, 0.f, 0.f);
    #pragma unroll 5
    for (int i = 0; i < SS / SCH; i++) {
        float ws = w[s0 + i];
        float4 v = *(const float4*)(base + (size_t)idx[i] * EE + cc);
        acc.x = fmaf(ws, v.x, acc.x); acc.y = fmaf(ws, v.y, acc.y);
        acc.z = fmaf(ws, v.z, acc.z); acc.w = fmaf(ws, v.w, acc.w);
    }
    *(float4*)(g_cpart + ((size_t)y * BB + b) * HH + tid * 4) = acc;
}

// ---------------- 5. build x = [emb_out[tgt] | sum ctx partials] ----------------
__global__ __launch_bounds__(256) void build_x_kernel(
    const int* __restrict__ tgt, const float* __restrict__ emb_out)
{
    int b = blockIdx.x;
    int t = threadIdx.x;
    float4* dst = (float4*)(g_x + b * (EE + HH));
    if (t < 128) {
        const float4* w = (const float4*)(emb_out + (size_t)tgt[b] * EE);
        dst[t] = w[t];
    }
    float4 s = make_float4(0.f, 0.f, 0.f, 0.f);
    #pragma unroll
    for (int y = 0; y < SCH; y++) {
        float4 v = *(const float4*)(g_cpart + ((size_t)y * BB + b) * HH + t * 4);
        s = f4add(s, v);
    }
    dst[128 + t] = s;
}

// ---------------- 7. projection via mma.sync tf32, 3-stage, 2 CTA/SM ----------------
#define PSTAGES 3
#define PROJ_SMEM (PSTAGES * PBUF * 4)

__global__ __launch_bounds__(256, 2) void proj_mma_kernel(
    const float* __restrict__ A, const float* __restrict__ Bm,
    const float* __restrict__ bias, float* __restrict__ C)
{
    extern __shared__ float sm[];
    const int tid  = threadIdx.x;
    const int wid  = tid >> 5;
    const int lane = tid & 31;
    const int n0   = blockIdx.x * 128;
    const int wm   = wid & 1;
    const int wn   = wid >> 1;
    const int lrow = tid >> 3;
    const int lf4  = tid & 7;

    float d[2][4][4];
    #pragma unroll
    for (int i = 0; i < 2; i++)
        #pragma unroll
        for (int j = 0; j < 4; j++)
            #pragma unroll
            for (int k = 0; k < 4; k++) d[i][j][k] = 0.f;

    auto load_tile = [&](int buf, int kb) {
        float* as = sm + buf * PBUF;
        float* bs = as + 64 * PLDA;
        #pragma unroll
        for (int i = 0; i < 2; i++) {
            int row = lrow + i * 32;
            cp_async16(smem_u32(&as[row * PLDA + lf4 * 4]),
                       &A[(size_t)row * HH + kb + lf4 * 4]);
        }
        #pragma unroll
        for (int i = 0; i < 4; i++) {
            int row = lrow + i * 32;
            cp_async16(smem_u32(&bs[row * PLDA + lf4 * 4]),
                       &Bm[(size_t)(n0 + row) * HH + kb + lf4 * 4]);
        }
        cp_commit();
    };

    const int NT = HH / 32;             // 32 tiles
    load_tile(0, 0);
    load_tile(1, 32);

    int buf = 0;
    for (int t = 0; t < NT; t++) {
        if (t + 2 < NT) {
            int nb = buf + 2; if (nb >= PSTAGES) nb -= PSTAGES;
            load_tile(nb, (t + 2) * 32);
        } else cp_commit();
        cp_wait2();
        __syncthreads();

        const float* as = sm + buf * PBUF;
        const float* bs = as + 64 * PLDA;
        const int r = lane >> 2, c = lane & 3;
        #pragma unroll
        for (int k8 = 0; k8 < 4; k8++) {
            int kc = k8 * 8;
            uint32_t af[2][4], bf[4][2];
            #pragma unroll
            for (int mm = 0; mm < 2; mm++) {
                int mb = wm * 32 + mm * 16;
                af[mm][0] = f2tf32(as[(mb + r)     * PLDA + kc + c]);
                af[mm][1] = f2tf32(as[(mb + r + 8) * PLDA + kc + c]);
                af[mm][2] = f2tf32(as[(mb + r)     * PLDA + kc + c + 4]);
                af[mm][3] = f2tf32(as[(mb + r + 8) * PLDA + kc + c + 4]);
            }
            #pragma unroll
            for (int nn = 0; nn < 4; nn++) {
                int nb = wn * 32 + nn * 8;
                bf[nn][0] = f2tf32(bs[(nb + r) * PLDA + kc + c]);
                bf[nn][1] = f2tf32(bs[(nb + r) * PLDA + kc + c + 4]);
            }
            #pragma unroll
            for (int mm = 0; mm < 2; mm++)
                #pragma unroll
                for (int nn = 0; nn < 4; nn++)
                    mma_tf32(d[mm][nn], af[mm], bf[nn]);
        }
        __syncthreads();
        if (++buf == PSTAGES) buf = 0;
    }

    #pragma unroll
    for (int mm = 0; mm < 2; mm++) {
        int m = wm * 32 + mm * 16 + (lane >> 2);
        #pragma unroll
        for (int nn = 0; nn < 4; nn++) {
            int n = n0 + wn * 32 + nn * 8 + (lane & 3) * 2;
            float2 bv = *(const float2*)&bias[n];
            *(float2*)&C[(size_t)m * VT + n] =
                make_float2(d[mm][nn][0] + bv.x, d[mm][nn][1] + bv.y);
            *(float2*)&C[(size_t)(m + 8) * VT + n] =
                make_float2(d[mm][nn][2] + bv.x, d[mm][nn][3] + bv.y);
        }
    }
}

// ---------------- launch ----------------
extern "C" void kernel_launch(void* const* d_in, const int* in_sizes, int n_in,
                              void* d_out, int out_size)
{
    const int* src = (const int*)d_in[0];
    const int* pos = (const int*)d_in[1];
    const int* tgt = (const int*)d_in[2];

    int iE = -1;
    for (int i = 3; i < n_in; i++) {
        if (in_sizes[i] == 32000 * 512) { iE = i; break; }
    }
    const float* emb_in  = (const float*)d_in[iE + 0];
    const float* emb_out = (const float*)d_in[iE + 1];
    const float* emb_pos = (const float*)d_in[iE + 2];
    const float* W_scale = (const float*)d_in[iE + 3];
    const float* b_scale = (const float*)d_in[iE + 4];
    const float* W_ih    = (const float*)d_in[iE + 5];
    const float* b_ih    = (const float*)d_in[iE + 6];
    const float* W_hh    = (const float*)d_in[iE + 7];
    const float* b_hh    = (const float*)d_in[iE + 8];
    const float* W_proj  = (const float*)d_in[iE + 9];
    const float* b_proj  = (const float*)d_in[iE + 10];

    float* out = (float*)d_out;            // [B,VT]
    float* h   = out + (size_t)BB * VT;    // [B,H]

    float* g_mean_p, *g_x_p, *g_part_p, *g_h0_p;
    cudaGetSymbolAddress((void**)&g_mean_p, g_mean);
    cudaGetSymbolAddress((void**)&g_h0_p,   g_h0);
    cudaGetSymbolAddress((void**)&g_x_p,    g_x);
    cudaGetSymbolAddress((void**)&g_part_p, g_part);

    cudaFuncSetAttribute(proj_mma_kernel,
                         cudaFuncAttributeMaxDynamicSharedMemorySize, PROJ_SMEM);
    cudaFuncSetAttribute(gemm64tc_kernel,
                         cudaFuncAttributeMaxDynamicSharedMemorySize, GTC_SMEM);

    const int RED_GRID = (64 * HH / 4) / 64;   // 256 blocks

    // 2. mean over S (gather partials + reduce)
    mean_part_kernel<<<dim3(BB, SCH), 256>>>(src, pos, emb_in, emb_pos);
    mean_red_kernel<<<BB, 256>>>();
    // 3. h0 = mean @ W_scale^T + b_scale (tf32 split-K)
    gemm64tc_kernel<<<dim3(HH / 128, NSPLIT), 256, GTC_SMEM>>>(
        g_mean_p, W_scale, HH, nullptr, nullptr, 0,
        g_part_p, HH, HH / NSPLIT);
    reduce_part_kernel<<<RED_GRID, 256>>>(b_scale, nullptr, g_h0_p, HH, 0);
    // 4. attention
    energy_kernel<<<dim3(BB, (SS + 7) / 8), 256>>>(src, pos, emb_in, emb_pos);
    ctx_part_kernel<<<dim3(BB, SCH), 256>>>(src, pos, emb_in, emb_pos);
    // 5. x = [emb_out[tgt] | ctx]
    build_x_kernel<<<BB, 256>>>(tgt, emb_out);
    // 6. h = tanh(x @ W_ih^T + h0 @ W_hh^T + b) (tf32 split-K)
    gemm64tc_kernel<<<dim3(HH / 128, NSPLIT), 256, GTC_SMEM>>>(
        g_x_p, W_ih, EE + HH, g_h0_p, W_hh, HH,
        g_part_p, HH, (EE + HH + HH) / NSPLIT);
    reduce_part_kernel<<<RED_GRID, 256>>>(b_ih, b_hh, h, HH, 1);
    // 7. out = h @ W_proj^T + b_proj (tf32 mma, 3-stage, 2 CTA/SM)
    proj_mma_kernel<<<VT / 128, 256, PROJ_SMEM>>>(h, W_proj, b_proj, out);

    (void)out_size;
}